// round 1
// baseline (speedup 1.0000x reference)
#include <cuda_runtime.h>
#include <cuda_bf16.h>
#include <cstdint>

// LongformerAttention_44315472560501
//
// Reference semantics (long-sequence path):
//   output            = hidden_states               (identity copy, B*S*H f32)
//   attention_weights = zeros(B, S, S)              (B*S*S f32)
// d_out holds the flattened outputs; copy the first in_sizes[0] elements from
// hidden_states, zero the rest. Pure HBM-streaming kernel, float4 vectorized.

__global__ void copy_and_zero_v4(const float4* __restrict__ src,
                                 float4* __restrict__ dst,
                                 long long n_copy4,   // float4 count to copy
                                 long long n_total4)  // float4 count total
{
    long long i = (long long)blockIdx.x * blockDim.x + threadIdx.x;
    long long stride = (long long)gridDim.x * blockDim.x;
    const float4 z = make_float4(0.f, 0.f, 0.f, 0.f);
    for (; i < n_total4; i += stride) {
        dst[i] = (i < n_copy4) ? src[i] : z;
    }
}

__global__ void tail_scalar(const float* __restrict__ src,
                            float* __restrict__ dst,
                            long long start,
                            long long n_copy,
                            long long n_total)
{
    long long i = start + blockIdx.x * blockDim.x + threadIdx.x;
    if (i < n_total) {
        dst[i] = (i < n_copy) ? src[i] : 0.f;
    }
}

extern "C" void kernel_launch(void* const* d_in, const int* in_sizes, int n_in,
                              void* d_out, int out_size)
{
    const float* hidden = (const float*)d_in[0];
    float* out = (float*)d_out;

    long long n_total = (long long)out_size;
    long long n_copy  = (long long)in_sizes[0];
    if (n_copy > n_total) n_copy = n_total;

    long long n_total4 = n_total / 4;   // vectorized portion
    long long n_copy4  = n_copy  / 4;   // src is 16B-aligned (cudaMalloc) and
                                        // n_copy here is a multiple of 4

    if (n_total4 > 0) {
        int threads = 256;
        // 148 SMs * 16 resident-ish blocks; grid-stride covers the rest.
        int blocks = 148 * 16;
        long long needed = (n_total4 + threads - 1) / threads;
        if ((long long)blocks > needed) blocks = (int)needed;
        copy_and_zero_v4<<<blocks, threads>>>(
            (const float4*)hidden, (float4*)out, n_copy4, n_total4);
    }

    long long done = n_total4 * 4;
    if (done < n_total) {
        long long rem = n_total - done;
        int threads = 128;
        int blocks = (int)((rem + threads - 1) / threads);
        tail_scalar<<<blocks, threads>>>(hidden, out, done, n_copy, n_total);
    }
}